// round 16
// baseline (speedup 1.0000x reference)
#include <cuda_runtime.h>
#include <cuda_fp16.h>
#include <cstdint>

// Involution2D on GB300 — round 16: round-15 (150.0us) with ONE change:
// k_inv 256 -> 512 threads per CTA (same 16-px tile, px loop split in half).
// k_inv was issue/latency-bound (50us vs ~25us smem-wavefront floor, issue 64%,
// occ 35%); this doubles warps/SM (24->48) at zero traffic/layout change.

#define BB   4
#define HH_  128
#define WW_  128
#define CC   256
#define CR   64
#define KKG  144
#define FF   256
#define NPIX (BB*HH_*WW_)   // 65536

__device__ __align__(16) float g_w_buf[(size_t)NPIX * KKG];
__device__ __align__(16) float g_xi_buf[(size_t)NPIX * FF];
__device__ __align__(16) unsigned int g_wiT_h[256 * 128];   // fp16x2 [f][c/2]
__device__ __align__(16) unsigned int g_wrT_h[64 * 128];    // fp16x2 [n][c/2]
__device__ __align__(16) unsigned int g_wsT_h[144 * 32];    // fp16x2 [f][k/2]

#define SW(o) ((o) ^ (((o) >> 3) & 0x70))

__device__ __forceinline__ uint32_t smem_to_u32(const void* p) {
    uint32_t a;
    asm("{ .reg .u64 t; cvta.to.shared.u64 t, %1; cvt.u32.u64 %0, t; }"
        : "=r"(a) : "l"(p));
    return a;
}
__device__ __forceinline__ uint32_t pack_h2(float a, float b) {
    __half2 H = __halves2half2(__float2half_rn(a), __float2half_rn(b));
    return *reinterpret_cast<uint32_t*>(&H);
}
__device__ __forceinline__ void split2h(float a, float b,
                                        uint32_t &hi, uint32_t &lo) {
    __half ha = __float2half_rn(a), hb = __float2half_rn(b);
    float la = a - __half2float(ha);
    float lb = b - __half2float(hb);
    __half2 H = __halves2half2(ha, hb);
    __half2 L = __halves2half2(__float2half_rn(la), __float2half_rn(lb));
    hi = *reinterpret_cast<uint32_t*>(&H);
    lo = *reinterpret_cast<uint32_t*>(&L);
}
__device__ __forceinline__ void cp_async16(uint32_t dst, const void* src) {
    asm volatile("{ .reg .u64 g; cvta.to.global.u64 g, %1;\n\t"
                 "cp.async.cg.shared.global [%0], [g], 16; }"
                 :: "r"(dst), "l"(src) : "memory");
}
__device__ __forceinline__ void cp_async16_z(uint32_t dst, const void* src, int sz) {
    asm volatile("{ .reg .u64 g; cvta.to.global.u64 g, %1;\n\t"
                 "cp.async.cg.shared.global [%0], [g], 16, %2; }"
                 :: "r"(dst), "l"(src), "r"(sz) : "memory");
}
#define CP_COMMIT() asm volatile("cp.async.commit_group;" ::: "memory")
#define CP_WAIT(n)  asm volatile("cp.async.wait_group %0;" :: "n"(n) : "memory")

__device__ __forceinline__ void ldsm4(uint32_t (&r)[4], const void* p) {
    uint32_t addr;
    asm("{ .reg .u64 t; cvta.to.shared.u64 t, %1; cvt.u32.u64 %0, t; }"
        : "=r"(addr) : "l"(p));
    asm volatile("ldmatrix.sync.aligned.m8n8.x4.shared.b16 {%0,%1,%2,%3}, [%4];"
                 : "=r"(r[0]), "=r"(r[1]), "=r"(r[2]), "=r"(r[3]) : "r"(addr));
}
__device__ __forceinline__ void mma16816(float (&d)[4], const uint32_t (&a)[4],
                                         uint32_t b0, uint32_t b1) {
    asm volatile(
        "mma.sync.aligned.m16n8k16.row.col.f32.f16.f16.f32 "
        "{%0,%1,%2,%3}, {%4,%5,%6,%7}, {%8,%9}, {%0,%1,%2,%3};"
        : "+f"(d[0]), "+f"(d[1]), "+f"(d[2]), "+f"(d[3])
        : "r"(a[0]), "r"(a[1]), "r"(a[2]), "r"(a[3]), "r"(b0), "r"(b1));
}

// ---------------- prep: weight transposes (178 blocks, 1 item/thread) ----------------
__global__ void __launch_bounds__(256)
k_prepw(const float* __restrict__ Wi, const float* __restrict__ Wr,
        const float* __restrict__ Ws)
{
    const int bid = blockIdx.x;
    const int t   = threadIdx.x;
    if (bid < 128) {
        int i = bid * 256 + t;                 // 32768 items
        int f = i >> 7, cp = i & 127;
        g_wiT_h[f * 128 + cp] = pack_h2(Wi[(size_t)(2 * cp) * 256 + f],
                                        Wi[(size_t)(2 * cp + 1) * 256 + f]);
    } else if (bid < 160) {
        int i = (bid - 128) * 256 + t;         // 8192 items
        int n = i >> 7, kp = i & 127;
        g_wrT_h[n * 128 + kp] = pack_h2(Wr[(2 * kp) * 64 + n],
                                        Wr[(2 * kp + 1) * 64 + n]);
    } else {
        int i = (bid - 160) * 256 + t;         // 4608 items
        if (i < 4608) {
            int f = i >> 5, kp = i & 31;
            g_wsT_h[f * 32 + kp] = pack_h2(Ws[(2 * kp) * 144 + f],
                                           Ws[(2 * kp + 1) * 144 + f]);
        }
    }
}

// ---------------- fused kernel: xi AND r/w, fp16 2-pass (round-15 proven) ----------------
#define FX_A_HI  0
#define FX_A_LO  8192
#define FX_BI    16384
#define FX_BR    49152
#define FX_BUF   57344
#define FX_SMEM  114688
#define FX_WS    0
#define FX_SC    18432
#define FX_SH    18688
#define FX_R_HI  18944
#define FX_R_LO  27136

__device__ __forceinline__ void fx_issue_B(uint32_t sb, int buf, int kb, int t)
{
    const uint32_t base = sb + buf * FX_BUF;
    const uint4* gih = (const uint4*)g_wiT_h;
    const uint4* grh = (const uint4*)g_wrT_h;
    #pragma unroll
    for (int it = 0; it < 8; ++it) {
        int gi = t + it * 256;
        int f = gi >> 3, c = gi & 7;
        cp_async16(base + FX_BI + SW(f * 128 + c * 16), gih + f * 32 + kb * 8 + c);
    }
    #pragma unroll
    for (int it = 0; it < 2; ++it) {
        int gi = t + it * 256;
        int n = gi >> 3, c = gi & 7;
        cp_async16(base + FX_BR + SW(n * 128 + c * 16), grh + n * 32 + kb * 8 + c);
    }
}
__device__ __forceinline__ void fx_ldg_A(const float* __restrict__ x, int p0,
                                         int kb, int t, float4 (&rA)[4])
{
    const float4* xs = (const float4*)x;
    #pragma unroll
    for (int it = 0; it < 4; ++it) {
        int gi = t + it * 256;
        int row = gi >> 4, c4 = gi & 15;
        rA[it] = xs[(size_t)(p0 + row) * 64 + kb * 16 + c4];
    }
}
__device__ __forceinline__ void fx_sts_A(char* smc, int buf, int t,
                                         const float4 (&rA)[4])
{
    char* base = smc + buf * FX_BUF;
    #pragma unroll
    for (int it = 0; it < 4; ++it) {
        int gi = t + it * 256;
        int row = gi >> 4, c4 = gi & 15;
        uint32_t h0, l0, h1, l1;
        split2h(rA[it].x, rA[it].y, h0, l0);
        split2h(rA[it].z, rA[it].w, h1, l1);
        uint32_t d = SW(row * 128 + c4 * 8);
        *(uint2*)(base + FX_A_HI + d) = make_uint2(h0, h1);
        *(uint2*)(base + FX_A_LO + d) = make_uint2(l0, l1);
    }
}

__global__ void __launch_bounds__(256, 2)
k_fused(const float* __restrict__ x, const float* __restrict__ bi,
        const float* __restrict__ br,   const float* __restrict__ gamma,
        const float* __restrict__ beta, const float* __restrict__ mean,
        const float* __restrict__ var,  const float* __restrict__ bs)
{
    extern __shared__ char smc[];
    const uint32_t sb = smem_to_u32(smc);
    const int t    = threadIdx.x;
    const int wid  = t >> 5;
    const int lane = t & 31;
    const int p0   = blockIdx.x * 64;
    const int wm   = wid >> 2;
    const int wn   = wid & 3;

    float4 rA[4];

    fx_ldg_A(x, p0, 0, t, rA);
    fx_issue_B(sb, 0, 0, t); CP_COMMIT();
    fx_sts_A(smc, 0, t, rA);
    fx_ldg_A(x, p0, 1, t, rA);
    fx_issue_B(sb, 1, 1, t); CP_COMMIT();
    fx_sts_A(smc, 1, t, rA);
    fx_ldg_A(x, p0, 2, t, rA);

    float acc[2][8][4];     // xi
    float acc1[2][2][4];    // GEMM1
    #pragma unroll
    for (int i = 0; i < 2; ++i) {
        #pragma unroll
        for (int j = 0; j < 8; ++j)
            #pragma unroll
            for (int q = 0; q < 4; ++q) acc[i][j][q] = 0.f;
        #pragma unroll
        for (int j = 0; j < 2; ++j)
            #pragma unroll
            for (int q = 0; q < 4; ++q) acc1[i][j][q] = 0.f;
    }

    const int lr    = lane & 15;
    const int lk    = (lane >> 4) * 16;
    const int arow  = wm * 32 + lr;
    const int brow  = wn * 64 + lr;
    const int brow1 = wn * 16 + lr;

    for (int kb = 0; kb < 4; ++kb) {
        if (kb < 3) CP_WAIT(1); else CP_WAIT(0);
        __syncthreads();
        char* base = smc + (kb & 1) * FX_BUF;
        #pragma unroll
        for (int k16 = 0; k16 < 4; ++k16) {
            const int ko = k16 * 32 + lk;
            uint32_t ah[2][4], al[2][4];
            #pragma unroll
            for (int i = 0; i < 2; ++i) {
                ldsm4(ah[i], base + FX_A_HI + SW((arow + i * 16) * 128 + ko));
                ldsm4(al[i], base + FX_A_LO + SW((arow + i * 16) * 128 + ko));
            }
            // GEMM1: x @ Wr (2-pass)
            {
                uint32_t bv[4];
                ldsm4(bv, base + FX_BR + SW(brow1 * 128 + ko));
                #pragma unroll
                for (int i = 0; i < 2; ++i) {
                    mma16816(acc1[i][0], ah[i], bv[0], bv[2]);
                    mma16816(acc1[i][1], ah[i], bv[1], bv[3]);
                    mma16816(acc1[i][0], al[i], bv[0], bv[2]);
                    mma16816(acc1[i][1], al[i], bv[1], bv[3]);
                }
            }
            // xi: x @ Wi (2-pass)
            #pragma unroll
            for (int j = 0; j < 4; ++j) {
                uint32_t bv[4];
                ldsm4(bv, base + FX_BI + SW((brow + j * 16) * 128 + ko));
                #pragma unroll
                for (int i = 0; i < 2; ++i) {
                    mma16816(acc[i][2*j],   ah[i], bv[0], bv[2]);
                    mma16816(acc[i][2*j+1], ah[i], bv[1], bv[3]);
                    mma16816(acc[i][2*j],   al[i], bv[0], bv[2]);
                    mma16816(acc[i][2*j+1], al[i], bv[1], bv[3]);
                }
            }
        }
        __syncthreads();
        if (kb + 2 < 4) {
            fx_sts_A(smc, kb & 1, t, rA);
            fx_issue_B(sb, kb & 1, kb + 2, t); CP_COMMIT();
            if (kb + 3 < 4) fx_ldg_A(x, p0, kb + 3, t, rA);
        }
    }
    // Ws into buf0 space (hides under epilogues)
    {
        const uint4* sh = (const uint4*)g_wsT_h;
        for (int i = t; i < 1152; i += 256) {
            int f = i >> 3, c = i & 7;
            cp_async16(sb + FX_WS + SW(f * 128 + c * 16), sh + i);
        }
        CP_COMMIT();
    }
    if (t < 64) {
        float s = gamma[t] * rsqrtf(var[t] + 1e-3f);
        *(float*)(smc + FX_SC + t * 4) = s;
        *(float*)(smc + FX_SH + t * 4) = (br[t] - mean[t]) * s + beta[t];
    }
    __syncthreads();

    const int g  = lane >> 2;
    const int t2 = (lane & 3) * 2;

    // epilogue 1: BN + relu, split r -> smem fp16 hi/lo
    #pragma unroll
    for (int i = 0; i < 2; ++i) {
        #pragma unroll
        for (int n8 = 0; n8 < 2; ++n8) {
            const int n0 = wn * 16 + n8 * 8 + t2;
            const float s0 = *(float*)(smc + FX_SC + n0 * 4);
            const float s1 = *(float*)(smc + FX_SC + (n0 + 1) * 4);
            const float h0 = *(float*)(smc + FX_SH + n0 * 4);
            const float h1 = *(float*)(smc + FX_SH + (n0 + 1) * 4);
            #pragma unroll
            for (int half = 0; half < 2; ++half) {
                const int m = wm * 32 + i * 16 + g + half * 8;
                float r0 = fmaxf(fmaf(acc1[i][n8][half * 2],     s0, h0), 0.f);
                float r1 = fmaxf(fmaf(acc1[i][n8][half * 2 + 1], s1, h1), 0.f);
                uint32_t hi, lo;
                split2h(r0, r1, hi, lo);
                uint32_t d = SW(m * 128 + n0 * 2);
                *(uint32_t*)(smc + FX_R_HI + d) = hi;
                *(uint32_t*)(smc + FX_R_LO + d) = lo;
            }
        }
    }

    // xi epilogue: acc -> g_xi_buf fp32 (+bi)
    #pragma unroll
    for (int i = 0; i < 2; ++i) {
        const int m = p0 + wm * 32 + i * 16 + g;
        #pragma unroll
        for (int j = 0; j < 8; ++j) {
            const int n = wn * 64 + j * 8 + t2;
            float b0 = bi[n], b1 = bi[n + 1];
            *(float2*)&g_xi_buf[(size_t)m * 256 + n] =
                make_float2(acc[i][j][0] + b0, acc[i][j][1] + b1);
            *(float2*)&g_xi_buf[(size_t)(m + 8) * 256 + n] =
                make_float2(acc[i][j][2] + b0, acc[i][j][3] + b1);
        }
    }

    CP_WAIT(0);
    __syncthreads();

    // GEMM2: w = r @ Ws + bs (2-pass, N=144, K=64)
    const int nblk = (wn == 3) ? 3 : 2;
    int blkid[3] = {wn, wn + 4, 8};
    float acc2[3][2][2][4];
    #pragma unroll
    for (int b = 0; b < 3; ++b)
        #pragma unroll
        for (int i = 0; i < 2; ++i)
            #pragma unroll
            for (int j = 0; j < 2; ++j)
                #pragma unroll
                for (int q = 0; q < 4; ++q) acc2[b][i][j][q] = 0.f;

    #pragma unroll
    for (int k16 = 0; k16 < 4; ++k16) {
        const int ko = k16 * 32 + lk;
        uint32_t ah[2][4], al[2][4];
        #pragma unroll
        for (int i = 0; i < 2; ++i) {
            ldsm4(ah[i], smc + FX_R_HI + SW((arow + i * 16) * 128 + ko));
            ldsm4(al[i], smc + FX_R_LO + SW((arow + i * 16) * 128 + ko));
        }
        for (int b = 0; b < nblk; ++b) {
            const int brw = blkid[b] * 16 + lr;
            uint32_t bv[4];
            ldsm4(bv, smc + FX_WS + SW(brw * 128 + ko));
            #pragma unroll
            for (int i = 0; i < 2; ++i) {
                mma16816(acc2[b][i][0], ah[i], bv[0], bv[2]);
                mma16816(acc2[b][i][1], ah[i], bv[1], bv[3]);
                mma16816(acc2[b][i][0], al[i], bv[0], bv[2]);
                mma16816(acc2[b][i][1], al[i], bv[1], bv[3]);
            }
        }
    }

    // epilogue 2: w -> g_w_buf (+bs)
    for (int b = 0; b < nblk; ++b) {
        #pragma unroll
        for (int j = 0; j < 2; ++j) {
            const int n = blkid[b] * 16 + j * 8 + t2;
            const float b0 = bs[n], b1 = bs[n + 1];
            #pragma unroll
            for (int i = 0; i < 2; ++i) {
                const int m = p0 + wm * 32 + i * 16 + g;
                *(float2*)&g_w_buf[(size_t)m * 144 + n] =
                    make_float2(acc2[b][i][j][0] + b0, acc2[b][i][j][1] + b1);
                *(float2*)&g_w_buf[(size_t)(m + 8) * 144 + n] =
                    make_float2(acc2[b][i][j][2] + b0, acc2[b][i][j][3] + b1);
            }
        }
    }
}

// ---------------- kernel: involution gather, 512 threads (px split) ----------------
#define INV_SMEM_FLOATS (3*18*256 + 16*144)

__global__ void __launch_bounds__(512)
k_inv(float* __restrict__ out)
{
    extern __shared__ float sm2[];
    float* xis = sm2;                       // [54][256]
    float* wsm = sm2 + 13824;               // [16][144]
    const uint32_t sb = smem_to_u32(sm2);

    const int t   = threadIdx.x;
    const int seg = blockIdx.x & 7;
    const int h   = (blockIdx.x >> 3) & 127;
    const int b   = blockIdx.x >> 10;
    const int w0  = seg * 16;
    const size_t prow = ((size_t)b * 128 + h) * 128;

    {
        const uint4* src = (const uint4*)(g_w_buf + (prow + w0) * 144);
        for (int i = t; i < 576; i += 512)
            cp_async16(sb + 55296 + i * 16, src + i);
    }
    for (int i = t; i < 3456; i += 512) {
        int pos = i >> 6, c4 = i & 63;
        int rr = pos / 18, cc = pos - rr * 18;
        int hhp = h - 1 + rr, wwp = w0 - 1 + cc;
        bool ok = ((unsigned)hhp < 128u) && ((unsigned)wwp < 128u);
        const uint4* s = ok
            ? (const uint4*)(g_xi_buf + (((size_t)b * 128 + hhp) * 128 + wwp) * 256) + c4
            : (const uint4*)g_xi_buf;
        cp_async16_z(sb + (uint32_t)(pos * 1024 + c4 * 16), s, ok ? 16 : 0);
    }
    CP_COMMIT();
    CP_WAIT(0);
    __syncthreads();

    const int o  = t & 255;                 // output channel
    const int ph = t >> 8;                  // pixel half: 0 or 1
    const int g  = o >> 4;
    const int fb = g * 144 + (o & 15) * 9;
    int off[9];
    #pragma unroll
    for (int kk = 0; kk < 9; kk++) {
        int flat = fb + kk;
        int kpos = flat >> 8;
        int c    = flat & 255;
        int di   = kpos / 3, dj = kpos - di * 3;
        off[kk]  = (di * 18 + dj) * 256 + c;
    }

    #pragma unroll
    for (int pi = 0; pi < 8; pi++) {
        const int px = ph * 8 + pi;
        const float* wp = &wsm[px * 144 + g * 9];
        const float* xb = &xis[px * 256];
        float acc = 0.f;
        #pragma unroll
        for (int kk = 0; kk < 9; kk++)
            acc = fmaf(wp[kk], xb[off[kk]], acc);
        out[(prow + w0 + px) * 256 + o] = acc;
    }
}

// ---------------- launch ----------------
extern "C" void kernel_launch(void* const* d_in, const int* in_sizes, int n_in,
                              void* d_out, int out_size)
{
    const float* x     = (const float*)d_in[0];
    const float* Wr    = (const float*)d_in[1];
    const float* br    = (const float*)d_in[2];
    const float* gamma = (const float*)d_in[3];
    const float* beta  = (const float*)d_in[4];
    const float* mean  = (const float*)d_in[5];
    const float* var   = (const float*)d_in[6];
    const float* Ws    = (const float*)d_in[7];
    const float* bs    = (const float*)d_in[8];
    const float* Wi    = (const float*)d_in[9];
    const float* bi    = (const float*)d_in[10];
    float* out = (float*)d_out;
    (void)in_sizes; (void)n_in; (void)out_size;

    const int smemF = FX_SMEM;                                  // 114,688
    const int smem2 = INV_SMEM_FLOATS * (int)sizeof(float);     // 64,512
    cudaFuncSetAttribute(k_fused, cudaFuncAttributeMaxDynamicSharedMemorySize, smemF);
    cudaFuncSetAttribute(k_inv,   cudaFuncAttributeMaxDynamicSharedMemorySize, smem2);

    k_prepw <<<178,        256>>>(Wi, Wr, Ws);
    k_fused <<<NPIX / 64,  256, smemF>>>(x, bi, br, gamma, beta, mean, var, bs);
    k_inv   <<<NPIX / 16,  512, smem2>>>(out);
}

// round 17
// speedup vs baseline: 1.1336x; 1.1336x over previous
#include <cuda_runtime.h>
#include <cuda_fp16.h>
#include <cstdint>

// Involution2D on GB300 — round 17: round-15 config (150.0us best) with ONE
// change: the r/w path (GEMM1, GEMM2) drops its lo-pass (single-pass fp16).
// xi keeps 2-pass. k_inv = proven round-7/15 version (4 perturbations all
// regressed; it is a local optimum).

#define BB   4
#define HH_  128
#define WW_  128
#define CC   256
#define CR   64
#define KKG  144
#define FF   256
#define NPIX (BB*HH_*WW_)   // 65536

__device__ __align__(16) float g_w_buf[(size_t)NPIX * KKG];
__device__ __align__(16) float g_xi_buf[(size_t)NPIX * FF];
__device__ __align__(16) unsigned int g_wiT_h[256 * 128];   // fp16x2 [f][c/2]
__device__ __align__(16) unsigned int g_wrT_h[64 * 128];    // fp16x2 [n][c/2]
__device__ __align__(16) unsigned int g_wsT_h[144 * 32];    // fp16x2 [f][k/2]

#define SW(o) ((o) ^ (((o) >> 3) & 0x70))

__device__ __forceinline__ uint32_t smem_to_u32(const void* p) {
    uint32_t a;
    asm("{ .reg .u64 t; cvta.to.shared.u64 t, %1; cvt.u32.u64 %0, t; }"
        : "=r"(a) : "l"(p));
    return a;
}
__device__ __forceinline__ uint32_t pack_h2(float a, float b) {
    __half2 H = __halves2half2(__float2half_rn(a), __float2half_rn(b));
    return *reinterpret_cast<uint32_t*>(&H);
}
__device__ __forceinline__ void split2h(float a, float b,
                                        uint32_t &hi, uint32_t &lo) {
    __half ha = __float2half_rn(a), hb = __float2half_rn(b);
    float la = a - __half2float(ha);
    float lb = b - __half2float(hb);
    __half2 H = __halves2half2(ha, hb);
    __half2 L = __halves2half2(__float2half_rn(la), __float2half_rn(lb));
    hi = *reinterpret_cast<uint32_t*>(&H);
    lo = *reinterpret_cast<uint32_t*>(&L);
}
__device__ __forceinline__ void cp_async16(uint32_t dst, const void* src) {
    asm volatile("{ .reg .u64 g; cvta.to.global.u64 g, %1;\n\t"
                 "cp.async.cg.shared.global [%0], [g], 16; }"
                 :: "r"(dst), "l"(src) : "memory");
}
__device__ __forceinline__ void cp_async16_z(uint32_t dst, const void* src, int sz) {
    asm volatile("{ .reg .u64 g; cvta.to.global.u64 g, %1;\n\t"
                 "cp.async.cg.shared.global [%0], [g], 16, %2; }"
                 :: "r"(dst), "l"(src), "r"(sz) : "memory");
}
#define CP_COMMIT() asm volatile("cp.async.commit_group;" ::: "memory")
#define CP_WAIT(n)  asm volatile("cp.async.wait_group %0;" :: "n"(n) : "memory")

__device__ __forceinline__ void ldsm4(uint32_t (&r)[4], const void* p) {
    uint32_t addr;
    asm("{ .reg .u64 t; cvta.to.shared.u64 t, %1; cvt.u32.u64 %0, t; }"
        : "=r"(addr) : "l"(p));
    asm volatile("ldmatrix.sync.aligned.m8n8.x4.shared.b16 {%0,%1,%2,%3}, [%4];"
                 : "=r"(r[0]), "=r"(r[1]), "=r"(r[2]), "=r"(r[3]) : "r"(addr));
}
__device__ __forceinline__ void mma16816(float (&d)[4], const uint32_t (&a)[4],
                                         uint32_t b0, uint32_t b1) {
    asm volatile(
        "mma.sync.aligned.m16n8k16.row.col.f32.f16.f16.f32 "
        "{%0,%1,%2,%3}, {%4,%5,%6,%7}, {%8,%9}, {%0,%1,%2,%3};"
        : "+f"(d[0]), "+f"(d[1]), "+f"(d[2]), "+f"(d[3])
        : "r"(a[0]), "r"(a[1]), "r"(a[2]), "r"(a[3]), "r"(b0), "r"(b1));
}

// ---------------- prep: weight transposes (178 blocks, 1 item/thread) ----------------
__global__ void __launch_bounds__(256)
k_prepw(const float* __restrict__ Wi, const float* __restrict__ Wr,
        const float* __restrict__ Ws)
{
    const int bid = blockIdx.x;
    const int t   = threadIdx.x;
    if (bid < 128) {
        int i = bid * 256 + t;                 // 32768 items
        int f = i >> 7, cp = i & 127;
        g_wiT_h[f * 128 + cp] = pack_h2(Wi[(size_t)(2 * cp) * 256 + f],
                                        Wi[(size_t)(2 * cp + 1) * 256 + f]);
    } else if (bid < 160) {
        int i = (bid - 128) * 256 + t;         // 8192 items
        int n = i >> 7, kp = i & 127;
        g_wrT_h[n * 128 + kp] = pack_h2(Wr[(2 * kp) * 64 + n],
                                        Wr[(2 * kp + 1) * 64 + n]);
    } else {
        int i = (bid - 160) * 256 + t;         // 4608 items
        if (i < 4608) {
            int f = i >> 5, kp = i & 31;
            g_wsT_h[f * 32 + kp] = pack_h2(Ws[(2 * kp) * 144 + f],
                                           Ws[(2 * kp + 1) * 144 + f]);
        }
    }
}

// ---------------- fused kernel: xi (2-pass) AND r/w (1-pass) ----------------
#define FX_A_HI  0
#define FX_A_LO  8192
#define FX_BI    16384
#define FX_BR    49152
#define FX_BUF   57344
#define FX_SMEM  114688
#define FX_WS    0
#define FX_SC    18432
#define FX_SH    18688
#define FX_R_HI  18944

__device__ __forceinline__ void fx_issue_B(uint32_t sb, int buf, int kb, int t)
{
    const uint32_t base = sb + buf * FX_BUF;
    const uint4* gih = (const uint4*)g_wiT_h;
    const uint4* grh = (const uint4*)g_wrT_h;
    #pragma unroll
    for (int it = 0; it < 8; ++it) {
        int gi = t + it * 256;
        int f = gi >> 3, c = gi & 7;
        cp_async16(base + FX_BI + SW(f * 128 + c * 16), gih + f * 32 + kb * 8 + c);
    }
    #pragma unroll
    for (int it = 0; it < 2; ++it) {
        int gi = t + it * 256;
        int n = gi >> 3, c = gi & 7;
        cp_async16(base + FX_BR + SW(n * 128 + c * 16), grh + n * 32 + kb * 8 + c);
    }
}
__device__ __forceinline__ void fx_ldg_A(const float* __restrict__ x, int p0,
                                         int kb, int t, float4 (&rA)[4])
{
    const float4* xs = (const float4*)x;
    #pragma unroll
    for (int it = 0; it < 4; ++it) {
        int gi = t + it * 256;
        int row = gi >> 4, c4 = gi & 15;
        rA[it] = xs[(size_t)(p0 + row) * 64 + kb * 16 + c4];
    }
}
__device__ __forceinline__ void fx_sts_A(char* smc, int buf, int t,
                                         const float4 (&rA)[4])
{
    char* base = smc + buf * FX_BUF;
    #pragma unroll
    for (int it = 0; it < 4; ++it) {
        int gi = t + it * 256;
        int row = gi >> 4, c4 = gi & 15;
        uint32_t h0, l0, h1, l1;
        split2h(rA[it].x, rA[it].y, h0, l0);
        split2h(rA[it].z, rA[it].w, h1, l1);
        uint32_t d = SW(row * 128 + c4 * 8);
        *(uint2*)(base + FX_A_HI + d) = make_uint2(h0, h1);
        *(uint2*)(base + FX_A_LO + d) = make_uint2(l0, l1);
    }
}

__global__ void __launch_bounds__(256, 2)
k_fused(const float* __restrict__ x, const float* __restrict__ bi,
        const float* __restrict__ br,   const float* __restrict__ gamma,
        const float* __restrict__ beta, const float* __restrict__ mean,
        const float* __restrict__ var,  const float* __restrict__ bs)
{
    extern __shared__ char smc[];
    const uint32_t sb = smem_to_u32(smc);
    const int t    = threadIdx.x;
    const int wid  = t >> 5;
    const int lane = t & 31;
    const int p0   = blockIdx.x * 64;
    const int wm   = wid >> 2;
    const int wn   = wid & 3;

    float4 rA[4];

    fx_ldg_A(x, p0, 0, t, rA);
    fx_issue_B(sb, 0, 0, t); CP_COMMIT();
    fx_sts_A(smc, 0, t, rA);
    fx_ldg_A(x, p0, 1, t, rA);
    fx_issue_B(sb, 1, 1, t); CP_COMMIT();
    fx_sts_A(smc, 1, t, rA);
    fx_ldg_A(x, p0, 2, t, rA);

    float acc[2][8][4];     // xi
    float acc1[2][2][4];    // GEMM1
    #pragma unroll
    for (int i = 0; i < 2; ++i) {
        #pragma unroll
        for (int j = 0; j < 8; ++j)
            #pragma unroll
            for (int q = 0; q < 4; ++q) acc[i][j][q] = 0.f;
        #pragma unroll
        for (int j = 0; j < 2; ++j)
            #pragma unroll
            for (int q = 0; q < 4; ++q) acc1[i][j][q] = 0.f;
    }

    const int lr    = lane & 15;
    const int lk    = (lane >> 4) * 16;
    const int arow  = wm * 32 + lr;
    const int brow  = wn * 64 + lr;
    const int brow1 = wn * 16 + lr;

    for (int kb = 0; kb < 4; ++kb) {
        if (kb < 3) CP_WAIT(1); else CP_WAIT(0);
        __syncthreads();
        char* base = smc + (kb & 1) * FX_BUF;
        #pragma unroll
        for (int k16 = 0; k16 < 4; ++k16) {
            const int ko = k16 * 32 + lk;
            uint32_t ah[2][4], al[2][4];
            #pragma unroll
            for (int i = 0; i < 2; ++i) {
                ldsm4(ah[i], base + FX_A_HI + SW((arow + i * 16) * 128 + ko));
                ldsm4(al[i], base + FX_A_LO + SW((arow + i * 16) * 128 + ko));
            }
            // GEMM1: x @ Wr (single-pass fp16)
            {
                uint32_t bv[4];
                ldsm4(bv, base + FX_BR + SW(brow1 * 128 + ko));
                #pragma unroll
                for (int i = 0; i < 2; ++i) {
                    mma16816(acc1[i][0], ah[i], bv[0], bv[2]);
                    mma16816(acc1[i][1], ah[i], bv[1], bv[3]);
                }
            }
            // xi: x @ Wi (2-pass)
            #pragma unroll
            for (int j = 0; j < 4; ++j) {
                uint32_t bv[4];
                ldsm4(bv, base + FX_BI + SW((brow + j * 16) * 128 + ko));
                #pragma unroll
                for (int i = 0; i < 2; ++i) {
                    mma16816(acc[i][2*j],   ah[i], bv[0], bv[2]);
                    mma16816(acc[i][2*j+1], ah[i], bv[1], bv[3]);
                    mma16816(acc[i][2*j],   al[i], bv[0], bv[2]);
                    mma16816(acc[i][2*j+1], al[i], bv[1], bv[3]);
                }
            }
        }
        __syncthreads();
        if (kb + 2 < 4) {
            fx_sts_A(smc, kb & 1, t, rA);
            fx_issue_B(sb, kb & 1, kb + 2, t); CP_COMMIT();
            if (kb + 3 < 4) fx_ldg_A(x, p0, kb + 3, t, rA);
        }
    }
    // Ws into buf0 space (hides under epilogues)
    {
        const uint4* sh = (const uint4*)g_wsT_h;
        for (int i = t; i < 1152; i += 256) {
            int f = i >> 3, c = i & 7;
            cp_async16(sb + FX_WS + SW(f * 128 + c * 16), sh + i);
        }
        CP_COMMIT();
    }
    if (t < 64) {
        float s = gamma[t] * rsqrtf(var[t] + 1e-3f);
        *(float*)(smc + FX_SC + t * 4) = s;
        *(float*)(smc + FX_SH + t * 4) = (br[t] - mean[t]) * s + beta[t];
    }
    __syncthreads();

    const int g  = lane >> 2;
    const int t2 = (lane & 3) * 2;

    // epilogue 1: BN + relu, r -> smem fp16 (single precision level)
    #pragma unroll
    for (int i = 0; i < 2; ++i) {
        #pragma unroll
        for (int n8 = 0; n8 < 2; ++n8) {
            const int n0 = wn * 16 + n8 * 8 + t2;
            const float s0 = *(float*)(smc + FX_SC + n0 * 4);
            const float s1 = *(float*)(smc + FX_SC + (n0 + 1) * 4);
            const float h0 = *(float*)(smc + FX_SH + n0 * 4);
            const float h1 = *(float*)(smc + FX_SH + (n0 + 1) * 4);
            #pragma unroll
            for (int half = 0; half < 2; ++half) {
                const int m = wm * 32 + i * 16 + g + half * 8;
                float r0 = fmaxf(fmaf(acc1[i][n8][half * 2],     s0, h0), 0.f);
                float r1 = fmaxf(fmaf(acc1[i][n8][half * 2 + 1], s1, h1), 0.f);
                uint32_t d = SW(m * 128 + n0 * 2);
                *(uint32_t*)(smc + FX_R_HI + d) = pack_h2(r0, r1);
            }
        }
    }

    // xi epilogue: acc -> g_xi_buf fp32 (+bi)
    #pragma unroll
    for (int i = 0; i < 2; ++i) {
        const int m = p0 + wm * 32 + i * 16 + g;
        #pragma unroll
        for (int j = 0; j < 8; ++j) {
            const int n = wn * 64 + j * 8 + t2;
            float b0 = bi[n], b1 = bi[n + 1];
            *(float2*)&g_xi_buf[(size_t)m * 256 + n] =
                make_float2(acc[i][j][0] + b0, acc[i][j][1] + b1);
            *(float2*)&g_xi_buf[(size_t)(m + 8) * 256 + n] =
                make_float2(acc[i][j][2] + b0, acc[i][j][3] + b1);
        }
    }

    CP_WAIT(0);
    __syncthreads();

    // GEMM2: w = r @ Ws + bs (single-pass fp16, N=144, K=64)
    const int nblk = (wn == 3) ? 3 : 2;
    int blkid[3] = {wn, wn + 4, 8};
    float acc2[3][2][2][4];
    #pragma unroll
    for (int b = 0; b < 3; ++b)
        #pragma unroll
        for (int i = 0; i < 2; ++i)
            #pragma unroll
            for (int j = 0; j < 2; ++j)
                #pragma unroll
                for (int q = 0; q < 4; ++q) acc2[b][i][j][q] = 0.f;

    #pragma unroll
    for (int k16 = 0; k16 < 4; ++k16) {
        const int ko = k16 * 32 + lk;
        uint32_t ah[2][4];
        #pragma unroll
        for (int i = 0; i < 2; ++i)
            ldsm4(ah[i], smc + FX_R_HI + SW((arow + i * 16) * 128 + ko));
        for (int b = 0; b < nblk; ++b) {
            const int brw = blkid[b] * 16 + lr;
            uint32_t bv[4];
            ldsm4(bv, smc + FX_WS + SW(brw * 128 + ko));
            #pragma unroll
            for (int i = 0; i < 2; ++i) {
                mma16816(acc2[b][i][0], ah[i], bv[0], bv[2]);
                mma16816(acc2[b][i][1], ah[i], bv[1], bv[3]);
            }
        }
    }

    // epilogue 2: w -> g_w_buf (+bs)
    for (int b = 0; b < nblk; ++b) {
        #pragma unroll
        for (int j = 0; j < 2; ++j) {
            const int n = blkid[b] * 16 + j * 8 + t2;
            const float b0 = bs[n], b1 = bs[n + 1];
            #pragma unroll
            for (int i = 0; i < 2; ++i) {
                const int m = p0 + wm * 32 + i * 16 + g;
                *(float2*)&g_w_buf[(size_t)m * 144 + n] =
                    make_float2(acc2[b][i][j][0] + b0, acc2[b][i][j][1] + b1);
                *(float2*)&g_w_buf[(size_t)(m + 8) * 144 + n] =
                    make_float2(acc2[b][i][j][2] + b0, acc2[b][i][j][3] + b1);
            }
        }
    }
}

// ---------------- kernel: involution gather (round-7/15 proven) ----------------
#define INV_SMEM_FLOATS (3*18*256 + 16*144)

__global__ void __launch_bounds__(256)
k_inv(float* __restrict__ out)
{
    extern __shared__ float sm2[];
    float* xis = sm2;                       // [54][256]
    float* wsm = sm2 + 13824;               // [16][144]
    const uint32_t sb = smem_to_u32(sm2);

    const int t   = threadIdx.x;
    const int seg = blockIdx.x & 7;
    const int h   = (blockIdx.x >> 3) & 127;
    const int b   = blockIdx.x >> 10;
    const int w0  = seg * 16;
    const size_t prow = ((size_t)b * 128 + h) * 128;

    {
        const uint4* src = (const uint4*)(g_w_buf + (prow + w0) * 144);
        for (int i = t; i < 576; i += 256)
            cp_async16(sb + 55296 + i * 16, src + i);
    }
    for (int i = t; i < 3456; i += 256) {
        int pos = i >> 6, c4 = i & 63;
        int rr = pos / 18, cc = pos - rr * 18;
        int hhp = h - 1 + rr, wwp = w0 - 1 + cc;
        bool ok = ((unsigned)hhp < 128u) && ((unsigned)wwp < 128u);
        const uint4* s = ok
            ? (const uint4*)(g_xi_buf + (((size_t)b * 128 + hhp) * 128 + wwp) * 256) + c4
            : (const uint4*)g_xi_buf;
        cp_async16_z(sb + (uint32_t)(pos * 1024 + c4 * 16), s, ok ? 16 : 0);
    }
    CP_COMMIT();
    CP_WAIT(0);
    __syncthreads();

    const int o  = t;
    const int g  = o >> 4;
    const int fb = g * 144 + (o & 15) * 9;
    int off[9];
    #pragma unroll
    for (int kk = 0; kk < 9; kk++) {
        int flat = fb + kk;
        int kpos = flat >> 8;
        int c    = flat & 255;
        int di   = kpos / 3, dj = kpos - di * 3;
        off[kk]  = (di * 18 + dj) * 256 + c;
    }

    for (int px = 0; px < 16; px++) {
        const float* wp = &wsm[px * 144 + g * 9];
        const float* xb = &xis[px * 256];
        float acc = 0.f;
        #pragma unroll
        for (int kk = 0; kk < 9; kk++)
            acc = fmaf(wp[kk], xb[off[kk]], acc);
        out[(prow + w0 + px) * 256 + o] = acc;
    }
}

// ---------------- launch ----------------
extern "C" void kernel_launch(void* const* d_in, const int* in_sizes, int n_in,
                              void* d_out, int out_size)
{
    const float* x     = (const float*)d_in[0];
    const float* Wr    = (const float*)d_in[1];
    const float* br    = (const float*)d_in[2];
    const float* gamma = (const float*)d_in[3];
    const float* beta  = (const float*)d_in[4];
    const float* mean  = (const float*)d_in[5];
    const float* var   = (const float*)d_in[6];
    const float* Ws    = (const float*)d_in[7];
    const float* bs    = (const float*)d_in[8];
    const float* Wi    = (const float*)d_in[9];
    const float* bi    = (const float*)d_in[10];
    float* out = (float*)d_out;
    (void)in_sizes; (void)n_in; (void)out_size;

    const int smemF = FX_SMEM;                                  // 114,688
    const int smem2 = INV_SMEM_FLOATS * (int)sizeof(float);     // 64,512
    cudaFuncSetAttribute(k_fused, cudaFuncAttributeMaxDynamicSharedMemorySize, smemF);
    cudaFuncSetAttribute(k_inv,   cudaFuncAttributeMaxDynamicSharedMemorySize, smem2);

    k_prepw <<<178,        256>>>(Wi, Wr, Ws);
    k_fused <<<NPIX / 64,  256, smemF>>>(x, bi, br, gamma, beta, mean, var, bs);
    k_inv   <<<NPIX / 16,  256, smem2>>>(out);
}